// round 9
// baseline (speedup 1.0000x reference)
#include <cuda_runtime.h>
#include <cuda_bf16.h>

// Problem: ToRGBLayer  (B=16, CIN=128, COUT=3, WDIM=512, H=W=256)
// out[b,o,h,w] = sum_i x[b,i,h,w] * style[b,i] * weight[o,i] + bias[o]
// style[b,i]   = dot(w[b,:], affine_w[i,:]) + affine_b[i]
//
// R9: torgb frozen at R8 config (512-thr blocks, 4 CTA/SM, unroll 4,
// __ldcs/__stcg — measured 81.0us = LTS/DRAM ceiling, converged).
// Style kernel shrunk: one warp computes 4 coeffs (same b, 4 consecutive i),
// reusing the w[b] row loads; 512 warps = 64 CTAs (was 256) -> PDL
// dependency releases sooner, exposure ~2.6 -> ~1.7us.

#define B_    16
#define CIN_  128
#define COUT_ 3
#define WDIM_ 512
#define HW_   65536            // 256*256
#define HW4_  16384            // HW/4 float4 positions

// Scratch: coeff[b][i] = {style*w0, style*w1, style*w2, 0}
__device__ float4 g_coeff[B_ * CIN_];

// ---------------------------------------------------------------------------
// Kernel 1: coeff. One warp per (b, 4 consecutive i). 512 warps = 64 CTAs.
// w[b] row loaded once per warp (16 regs), reused across 4 affine_w rows.
// ---------------------------------------------------------------------------
__global__ void __launch_bounds__(256) style_kernel(
    const float4* __restrict__ w,         // [B, WDIM/4]
    const float*  __restrict__ weight,    // [COUT, CIN] (1x1 conv squeezed)
    const float4* __restrict__ affine_w,  // [CIN, WDIM/4]
    const float*  __restrict__ affine_b)  // [CIN]
{
    const int lane = threadIdx.x & 31;
    const int gw   = (blockIdx.x << 3) + (threadIdx.x >> 5);  // 0..511
    const int b    = gw >> 5;              // / 32 groups  -> 0..15
    const int i0   = (gw & 31) << 2;       // first of 4 consecutive i

    const float4* wb = w + b * (WDIM_ / 4);

    // Load this batch's w row once: 4 float4 per lane.
    float4 a[4];
    #pragma unroll
    for (int k = 0; k < 4; k++) a[k] = wb[lane + 32 * k];

    #pragma unroll
    for (int j = 0; j < 4; j++) {
        const int i = i0 + j;
        const float4* aw = affine_w + i * (WDIM_ / 4);

        float acc = 0.f;
        #pragma unroll
        for (int k = 0; k < 4; k++) {
            float4 c = aw[lane + 32 * k];
            acc += a[k].x * c.x + a[k].y * c.y + a[k].z * c.z + a[k].w * c.w;
        }
        #pragma unroll
        for (int off = 16; off > 0; off >>= 1)
            acc += __shfl_down_sync(0xffffffffu, acc, off);

        if (lane == 0) {
            float style = acc + affine_b[i];
            float4 c;
            c.x = style * weight[0 * CIN_ + i];
            c.y = style * weight[1 * CIN_ + i];
            c.z = style * weight[2 * CIN_ + i];
            c.w = 0.f;
            g_coeff[b * CIN_ + i] = c;
        }
    }

    cudaTriggerProgrammaticLaunchCompletion();
}

// ---------------------------------------------------------------------------
// Kernel 2: streaming pass — FROZEN (R8 config, 81.0us, DRAM ceiling).
// grid = (HW4_/512, B) = (32,16), 512 threads, 4 CTA/SM, 32 regs.
// ---------------------------------------------------------------------------
__global__ void __launch_bounds__(512, 4) torgb_kernel(
    const float4* __restrict__ x,     // [B, CIN, HW4_] as float4
    const float*  __restrict__ bias,  // [COUT]
    float4*       __restrict__ out)   // [B, COUT, HW4_] as float4
{
    __shared__ float4 sc[CIN_];

    const int tid = threadIdx.x;
    const int b   = blockIdx.y;

    const size_t idx4 = (size_t)blockIdx.x * 512 + tid;
    const float4* xb  = x + ((size_t)b * CIN_) * HW4_ + idx4;

    cudaGridDependencySynchronize();

    if (tid < CIN_) sc[tid] = g_coeff[b * CIN_ + tid];
    __syncthreads();

    float4 a0 = make_float4(0.f, 0.f, 0.f, 0.f);
    float4 a1 = a0, a2 = a0;

    #pragma unroll 4
    for (int i = 0; i < CIN_; i++) {
        float4 v = __ldcs(&xb[(size_t)i * HW4_]);
        float4 c = sc[i];
        a0.x += v.x * c.x; a0.y += v.y * c.x; a0.z += v.z * c.x; a0.w += v.w * c.x;
        a1.x += v.x * c.y; a1.y += v.y * c.y; a1.z += v.z * c.y; a1.w += v.w * c.y;
        a2.x += v.x * c.z; a2.y += v.y * c.z; a2.z += v.z * c.z; a2.w += v.w * c.z;
    }

    const float b0 = bias[0], b1 = bias[1], b2 = bias[2];
    a0.x += b0; a0.y += b0; a0.z += b0; a0.w += b0;
    a1.x += b1; a1.y += b1; a1.z += b1; a1.w += b1;
    a2.x += b2; a2.y += b2; a2.z += b2; a2.w += b2;

    float4* ob = out + ((size_t)b * COUT_) * HW4_ + idx4;
    __stcg(&ob[0 * HW4_], a0);
    __stcg(&ob[1 * HW4_], a1);
    __stcg(&ob[2 * HW4_], a2);
}

// ---------------------------------------------------------------------------
// Launch. Input order (metadata): x, w, weight, bias, affine_w, affine_b
// ---------------------------------------------------------------------------
extern "C" void kernel_launch(void* const* d_in, const int* in_sizes, int n_in,
                              void* d_out, int out_size)
{
    const float*  x        = (const float*)d_in[0];
    const float*  w        = (const float*)d_in[1];
    const float*  weight   = (const float*)d_in[2];
    const float*  bias     = (const float*)d_in[3];
    const float*  affine_w = (const float*)d_in[4];
    const float*  affine_b = (const float*)d_in[5];
    float* out = (float*)d_out;

    style_kernel<<<64, 256>>>((const float4*)w, weight,
                              (const float4*)affine_w, affine_b);

    cudaLaunchConfig_t cfg = {};
    cfg.gridDim  = dim3(HW4_ / 512, B_);
    cfg.blockDim = dim3(512);
    cfg.dynamicSmemBytes = 0;
    cfg.stream = 0;

    cudaLaunchAttribute attrs[1];
    attrs[0].id = cudaLaunchAttributeProgrammaticStreamSerialization;
    attrs[0].val.programmaticStreamSerializationAllowed = 1;
    cfg.attrs = attrs;
    cfg.numAttrs = 1;

    cudaLaunchKernelEx(&cfg, torgb_kernel, (const float4*)x, bias, (float4*)out);
}

// round 11
// speedup vs baseline: 1.0248x; 1.0248x over previous
#include <cuda_runtime.h>
#include <cuda_bf16.h>

// Problem: ToRGBLayer  (B=16, CIN=128, COUT=3, WDIM=512, H=W=256)
// out[b,o,h,w] = sum_i x[b,i,h,w] * style[b,i] * weight[o,i] + bias[o]
// style[b,i]   = dot(w[b,:], affine_w[i,:]) + affine_b[i]
//
// R10: revert R9's style serialization (4 sequential dot chains per warp
// exposed 5us vs 2.6us; PDL waits on the slowest block). Back to the proven
// R8 pair: warp-per-(b,i) style (2048 independent warps, minimal critical
// path) + frozen torgb (512-thr blocks, 4 CTA/SM, unroll 4, __ldcs/__stcg,
// 32 regs — measured 79.7-81.8us across rounds = LTS/DRAM ceiling).

#define B_    16
#define CIN_  128
#define COUT_ 3
#define WDIM_ 512
#define HW_   65536            // 256*256
#define HW4_  16384            // HW/4 float4 positions

// Scratch: coeff[b][i] = {style*w0, style*w1, style*w2, 0}
__device__ float4 g_coeff[B_ * CIN_];

// ---------------------------------------------------------------------------
// Kernel 1: coeff. One warp per (b,i). 2048 warps = 256 blocks x 256 threads.
// Each warp: 8 independent LDG.128, 16 FMA, 5-shuffle reduce. Shortest
// possible critical path; all warps independent.
// ---------------------------------------------------------------------------
__global__ void __launch_bounds__(256) style_kernel(
    const float4* __restrict__ w,         // [B, WDIM/4]
    const float*  __restrict__ weight,    // [COUT, CIN] (1x1 conv squeezed)
    const float4* __restrict__ affine_w,  // [CIN, WDIM/4]
    const float*  __restrict__ affine_b)  // [CIN]
{
    const int lane = threadIdx.x & 31;
    const int gw   = (blockIdx.x << 3) + (threadIdx.x >> 5);  // global warp id
    const int b    = gw >> 7;          // / CIN_
    const int i    = gw & (CIN_ - 1);

    const float4* wb = w + b * (WDIM_ / 4);
    const float4* aw = affine_w + i * (WDIM_ / 4);

    float acc = 0.f;
    #pragma unroll
    for (int k = 0; k < 4; k++) {
        float4 a = wb[lane + 32 * k];
        float4 c = aw[lane + 32 * k];
        acc += a.x * c.x + a.y * c.y + a.z * c.z + a.w * c.w;
    }
    #pragma unroll
    for (int off = 16; off > 0; off >>= 1)
        acc += __shfl_down_sync(0xffffffffu, acc, off);

    if (lane == 0) {
        float style = acc + __ldg(&affine_b[i]);
        float4 c;
        c.x = style * __ldg(&weight[0 * CIN_ + i]);
        c.y = style * __ldg(&weight[1 * CIN_ + i]);
        c.z = style * __ldg(&weight[2 * CIN_ + i]);
        c.w = 0.f;
        g_coeff[b * CIN_ + i] = c;
    }

    cudaTriggerProgrammaticLaunchCompletion();
}

// ---------------------------------------------------------------------------
// Kernel 2: streaming pass — FROZEN (R8 config; 79.7-81.8us, DRAM ceiling).
// grid = (HW4_/512, B) = (32,16), 512 threads, 4 CTA/SM, 32 regs.
// ---------------------------------------------------------------------------
__global__ void __launch_bounds__(512, 4) torgb_kernel(
    const float4* __restrict__ x,     // [B, CIN, HW4_] as float4
    const float*  __restrict__ bias,  // [COUT]
    float4*       __restrict__ out)   // [B, COUT, HW4_] as float4
{
    __shared__ float4 sc[CIN_];

    const int tid = threadIdx.x;
    const int b   = blockIdx.y;

    const size_t idx4 = (size_t)blockIdx.x * 512 + tid;
    const float4* xb  = x + ((size_t)b * CIN_) * HW4_ + idx4;

    cudaGridDependencySynchronize();

    if (tid < CIN_) sc[tid] = g_coeff[b * CIN_ + tid];
    __syncthreads();

    float4 a0 = make_float4(0.f, 0.f, 0.f, 0.f);
    float4 a1 = a0, a2 = a0;

    #pragma unroll 4
    for (int i = 0; i < CIN_; i++) {
        float4 v = __ldcs(&xb[(size_t)i * HW4_]);
        float4 c = sc[i];
        a0.x += v.x * c.x; a0.y += v.y * c.x; a0.z += v.z * c.x; a0.w += v.w * c.x;
        a1.x += v.x * c.y; a1.y += v.y * c.y; a1.z += v.z * c.y; a1.w += v.w * c.y;
        a2.x += v.x * c.z; a2.y += v.y * c.z; a2.z += v.z * c.z; a2.w += v.w * c.z;
    }

    const float b0 = bias[0], b1 = bias[1], b2 = bias[2];
    a0.x += b0; a0.y += b0; a0.z += b0; a0.w += b0;
    a1.x += b1; a1.y += b1; a1.z += b1; a1.w += b1;
    a2.x += b2; a2.y += b2; a2.z += b2; a2.w += b2;

    float4* ob = out + ((size_t)b * COUT_) * HW4_ + idx4;
    __stcg(&ob[0 * HW4_], a0);
    __stcg(&ob[1 * HW4_], a1);
    __stcg(&ob[2 * HW4_], a2);
}

// ---------------------------------------------------------------------------
// Launch. Input order (metadata): x, w, weight, bias, affine_w, affine_b
// ---------------------------------------------------------------------------
extern "C" void kernel_launch(void* const* d_in, const int* in_sizes, int n_in,
                              void* d_out, int out_size)
{
    const float*  x        = (const float*)d_in[0];
    const float*  w        = (const float*)d_in[1];
    const float*  weight   = (const float*)d_in[2];
    const float*  bias     = (const float*)d_in[3];
    const float*  affine_w = (const float*)d_in[4];
    const float*  affine_b = (const float*)d_in[5];
    float* out = (float*)d_out;

    style_kernel<<<(B_ * CIN_) / 8, 256>>>((const float4*)w, weight,
                                           (const float4*)affine_w, affine_b);

    cudaLaunchConfig_t cfg = {};
    cfg.gridDim  = dim3(HW4_ / 512, B_);
    cfg.blockDim = dim3(512);
    cfg.dynamicSmemBytes = 0;
    cfg.stream = 0;

    cudaLaunchAttribute attrs[1];
    attrs[0].id = cudaLaunchAttributeProgrammaticStreamSerialization;
    attrs[0].val.programmaticStreamSerializationAllowed = 1;
    cfg.attrs = attrs;
    cfg.numAttrs = 1;

    cudaLaunchKernelEx(&cfg, torgb_kernel, (const float4*)x, bias, (float4*)out);
}